// round 10
// baseline (speedup 1.0000x reference)
#include <cuda_runtime.h>
#include <math.h>
#include <stdint.h>

#define EMBED 768
#define NB    8
#define SEQ   1024
#define ROWS  (NB*SEQ)   // 8192
#define HID   1536

// ---------------- scratch (__device__ globals; no allocs allowed) -----------
__device__ float g_V[(size_t)ROWS*EMBED];
__device__ float g_u[NB*EMBED];
__device__ float g_w[NB*EMBED];
__device__ float g_wb1[NB*HID];               // b1 + w[b] @ W1
__device__ float g_xrp[(size_t)ROWS*EMBED];   // perm(tf32(x))
__device__ float g_Hp[(size_t)ROWS*HID];      // perm(tf32(gelu(..))) from GEMM2
__device__ float g_M[(size_t)ROWS*EMBED];
__device__ float g_WvP[(size_t)EMBED*EMBED];  // perm B frags
__device__ float g_W1P[(size_t)HID*EMBED];
__device__ float g_W2P[(size_t)EMBED*HID];

// ---------------- helpers ----------------------------------------------------
__device__ __forceinline__ float f_tf32(float f) {
    uint32_t r;
    asm("cvt.rna.tf32.f32 %0, %1;" : "=r"(r) : "f"(f));
    return __uint_as_float(r);
}

// exact-GELU via Abramowitz-Stegun erf (abs err 1.5e-7)
__device__ __forceinline__ float gelu_f(float v) {
    float xs = v * 0.70710678118654752f;
    float ax = fabsf(xs);
    float t  = __frcp_rn(1.0f + 0.3275911f * ax);
    float poly = t * (0.254829592f + t * (-0.284496736f +
                 t * (1.421413741f + t * (-1.453152027f + t * 1.061405429f))));
    float erfv = 1.0f - poly * __expf(-ax * ax);
    erfv = copysignf(erfv, xs);
    return 0.5f * v * (1.0f + erfv);
}

__device__ __forceinline__ void mma_tf32(float c[4], const uint32_t a[4], const uint32_t b[2]) {
    asm volatile(
        "mma.sync.aligned.m16n8k8.row.col.f32.tf32.tf32.f32 "
        "{%0,%1,%2,%3}, {%4,%5,%6,%7}, {%8,%9}, {%0,%1,%2,%3};"
        : "+f"(c[0]), "+f"(c[1]), "+f"(c[2]), "+f"(c[3])
        : "r"(a[0]), "r"(a[1]), "r"(a[2]), "r"(a[3]), "r"(b[0]), "r"(b[1]));
}

__device__ __forceinline__ void cp16(uint32_t dst, const void* src) {
    asm volatile("cp.async.cg.shared.global [%0], [%1], 16;" :: "r"(dst), "l"(src));
}
__device__ __forceinline__ void cp_commit() {
    asm volatile("cp.async.commit_group;" ::: "memory");
}
template<int N> __device__ __forceinline__ void cp_wait() {
    asm volatile("cp.async.wait_group %0;" :: "n"(N) : "memory");
}

// ---------------- permuted-layout GEMM --------------------------------------
// A stored as fragment tiles: tile (rt=m/16, kt=k/8): 128 floats [lane][4],
//   slot0=(r,c) slot1=(r+8,c) slot2=(r,c+4) slot3=(r+8,c+4), r=lane>>2, c=lane&3
// B stored as: tile (nt=n/8, kt=k/8): 64 floats [lane][2],
//   slot0=(k=lane&3, n=lane>>2) slot1=(k+4, n)
// CTA 128x128, 128 thr (4 warps 2x2), warp tile 64x64, BK=32, 3-stage cp.async.
// 2 CTAs/SM -> 256 regs/thread budget: acc(128)+frags(32)+state fits, no spill.
// BBIAS: bias indexed per batch (bias + (rowBase>>10)*N).
// PERMOUT: write C in A-fragment-tile layout via smem staging (coalesced).
#define STG 3
#define STAGEF 8192                    // floats/stage: A 4096 + B 4096
#define GEMM_SMEM (STG * STAGEF * 4)   // 98304 B

template<bool BBIAS, bool BIAS, bool GELU, bool CVT, bool PERMOUT>
__global__ __launch_bounds__(128, 2)
void gemm_p(const float* __restrict__ Ap, const float* __restrict__ Bp,
            const float* __restrict__ bias, float* __restrict__ C,
            int M, int N, int K)
{
    extern __shared__ float sm[];
    const int tid  = threadIdx.x;
    const int lane = tid & 31;
    const int warp = tid >> 5;            // 0..3
    const int wm = (warp & 1) * 64;
    const int wn = (warp >> 1) * 64;
    const int rowBase = blockIdx.y * 128;
    const int colBase = blockIdx.x * 128;
    const int KT8 = K >> 3;
    const int rowTile0 = blockIdx.y * 8;
    const int colTile0 = blockIdx.x * 16;
    const uint32_t smBase = (uint32_t)__cvta_generic_to_shared(sm);

    float acc[4][8][4];
    #pragma unroll
    for (int i = 0; i < 4; i++)
        #pragma unroll
        for (int j = 0; j < 8; j++)
            #pragma unroll
            for (int c = 0; c < 4; c++) acc[i][j][c] = 0.f;

    const int NC = K >> 5;

    // stage copy: 1024 A cp16 + 1024 B cp16 by 128 threads (8 each)
    auto stage_copy = [&](int s, int ktBase) {
        const uint32_t aB = smBase + (uint32_t)(s * STAGEF * 4);
        const uint32_t bB = aB + 16384;
        #pragma unroll
        for (int u = 0; u < 8; u++) {
            const int i  = tid + 128 * u;
            const int rt = i >> 7, kt = (i >> 5) & 3, l = i & 31;
            cp16(aB + (uint32_t)i * 16,
                 Ap + ((size_t)(rowTile0 + rt) * KT8 + ktBase + kt) * 128 + l * 4);
        }
        #pragma unroll
        for (int u = 0; u < 8; u++) {
            const int j  = tid + 128 * u;
            const int nt = j >> 6, kt = (j >> 4) & 3, p = j & 15;
            cp16(bB + (uint32_t)j * 16,
                 Bp + ((size_t)(colTile0 + nt) * KT8 + ktBase + kt) * 64 + p * 4);
        }
        cp_commit();
    };

    stage_copy(0, 0);
    stage_copy(1, 4);

    for (int j = 0; j < NC; j++) {
        if (j + 1 < NC) cp_wait<1>(); else cp_wait<0>();
        __syncthreads();

        if (j + 2 < NC) stage_copy((j + 2) % STG, (j + 2) * 4);

        const float* As_ = sm + (j % STG) * STAGEF;
        const float* Bs_ = As_ + 4096;
        #pragma unroll
        for (int kt = 0; kt < 4; kt++) {
            uint32_t afr[4][4];
            #pragma unroll
            for (int mt = 0; mt < 4; mt++) {
                const float4 v = *(const float4*)(
                    As_ + (((warp & 1) * 4 + mt) * 4 + kt) * 128 + lane * 4);
                afr[mt][0] = __float_as_uint(v.x);
                afr[mt][1] = __float_as_uint(v.y);
                afr[mt][2] = __float_as_uint(v.z);
                afr[mt][3] = __float_as_uint(v.w);
            }
            uint32_t bfr[8][2];
            #pragma unroll
            for (int nt = 0; nt < 8; nt++) {
                const float2 v = *(const float2*)(
                    Bs_ + (((warp >> 1) * 8 + nt) * 4 + kt) * 64 + lane * 2);
                bfr[nt][0] = __float_as_uint(v.x);
                bfr[nt][1] = __float_as_uint(v.y);
            }
            #pragma unroll
            for (int mt = 0; mt < 4; mt++)
                #pragma unroll
                for (int nt = 0; nt < 8; nt++)
                    mma_tf32(acc[mt][nt], afr[mt], bfr[nt]);
        }
        __syncthreads();
    }

    // epilogue
    const float* bp = BBIAS ? (bias + (size_t)(rowBase >> 10) * N) : bias;

    if (PERMOUT) {
        // stage permuted tile in smem (pipeline stages are dead now), then
        // copy out with fully coalesced float4 stores.
        #pragma unroll
        for (int mt = 0; mt < 4; mt++) {
            const int rt_l = (warp & 1) * 4 + mt;       // local m-tile 0..7
            #pragma unroll
            for (int nt = 0; nt < 8; nt++) {
                const int kt_l = (warp >> 1) * 8 + nt;  // local k-tile 0..15
                const int col = colBase + wn + nt * 8 + 2 * (lane & 3);
                float v0 = acc[mt][nt][0], v1 = acc[mt][nt][1];
                float v2 = acc[mt][nt][2], v3 = acc[mt][nt][3];
                if (BIAS) {
                    float b0 = bp[col], b1v = bp[col + 1];
                    v0 += b0; v1 += b1v; v2 += b0; v3 += b1v;
                }
                if (GELU) {
                    v0 = gelu_f(v0); v1 = gelu_f(v1);
                    v2 = gelu_f(v2); v3 = gelu_f(v3);
                }
                if (CVT) {
                    v0 = f_tf32(v0); v1 = f_tf32(v1);
                    v2 = f_tf32(v2); v3 = f_tf32(v3);
                }
                float* base = sm + (rt_l * 16 + kt_l) * 128;
                const int r    = lane >> 2;
                const int cc   = 2 * (lane & 3);
                const int cp_  = cc & 3;
                const int slot = (cc < 4) ? 0 : 2;
                base[(4*r + cp_    ) * 4 + slot    ] = v0;
                base[(4*r + cp_ + 1) * 4 + slot    ] = v1;
                base[(4*r + cp_    ) * 4 + slot + 1] = v2;
                base[(4*r + cp_ + 1) * 4 + slot + 1] = v3;
            }
        }
        __syncthreads();
        // 8 rt-rows, each 16 tiles * 128 floats = 2048 floats contiguous in
        // both smem and global. 4096 float4 total / 128 threads = 32 each.
        #pragma unroll
        for (int u = 0; u < 32; u++) {
            const int i   = u * 128 + tid;
            const int rt  = i >> 9;          // 0..7
            const int idx = i & 511;         // float4 index within row
            const float4 v = ((const float4*)(sm + rt * 2048))[idx];
            ((float4*)(C + ((size_t)(rowTile0 + rt) * (N >> 3) + colTile0) * 128))[idx] = v;
        }
    } else {
        #pragma unroll
        for (int mt = 0; mt < 4; mt++) {
            const int r0 = rowBase + wm + mt * 16 + (lane >> 2);
            #pragma unroll
            for (int nt = 0; nt < 8; nt++) {
                const int col = colBase + wn + nt * 8 + 2 * (lane & 3);
                float v0 = acc[mt][nt][0], v1 = acc[mt][nt][1];
                float v2 = acc[mt][nt][2], v3 = acc[mt][nt][3];
                if (BIAS) {
                    float b0 = bp[col], b1v = bp[col + 1];
                    v0 += b0; v1 += b1v; v2 += b0; v3 += b1v;
                }
                if (GELU) {
                    v0 = gelu_f(v0); v1 = gelu_f(v1);
                    v2 = gelu_f(v2); v3 = gelu_f(v3);
                }
                if (CVT) {
                    v0 = f_tf32(v0); v1 = f_tf32(v1);
                    v2 = f_tf32(v2); v3 = f_tf32(v3);
                }
                *(float2*)(C + (size_t)r0 * N + col)       = make_float2(v0, v1);
                *(float2*)(C + (size_t)(r0 + 8) * N + col) = make_float2(v2, v3);
            }
        }
    }
}

// ---------------- perm A: [M,K] normal -> fragment tiles (+tf32) -------------
__global__ __launch_bounds__(256)
void perm_A(const float* __restrict__ in, float* __restrict__ out, int K)
{
    const size_t p4 = (size_t)blockIdx.x * 256 + threadIdx.x;  // one lane-quad
    const int KT8 = K >> 3;
    const size_t tile = p4 >> 5;
    const int l  = (int)(p4 & 31);
    const int rt = (int)(tile / KT8), kt = (int)(tile % KT8);
    const int r = rt * 16 + (l >> 2);
    const int c = kt * 8 + (l & 3);
    const float* row0 = in + (size_t)r * K;
    const float* row8 = row0 + (size_t)8 * K;
    float4 o;
    o.x = f_tf32(row0[c]);
    o.y = f_tf32(row8[c]);
    o.z = f_tf32(row0[c + 4]);
    o.w = f_tf32(row8[c + 4]);
    *(float4*)(out + p4 * 4) = o;
}

// ---------------- perm B: W[K,N] normal -> fragment tiles (+tf32) ------------
__global__ __launch_bounds__(256)
void perm_B(const float* __restrict__ W, float* __restrict__ out, int K, int N)
{
    const size_t p2 = (size_t)blockIdx.x * 256 + threadIdx.x;  // one lane-pair
    const int KT8 = K >> 3;
    const size_t tile = p2 >> 5;
    const int l  = (int)(p2 & 31);
    const int nt = (int)(tile / KT8), kt = (int)(tile % KT8);
    const int n = nt * 8 + (l >> 2);
    const int k = kt * 8 + (l & 3);
    float2 o;
    o.x = f_tf32(W[(size_t)k * N + n]);
    o.y = f_tf32(W[(size_t)(k + 4) * N + n]);
    *(float2*)(out + p2 * 2) = o;
}

// ---------------- vsum: u[b,n*64+d] = sum_s V_chunk[b,n][64*s+d] -------------
__global__ __launch_bounds__(512)
void vsum_kernel()
{
    const int bn  = blockIdx.x;
    const int tid = threadIdx.x;
    const int d    = tid & 63;
    const int part = tid >> 6;
    const float* base = g_V + (size_t)bn * 65536;

    float s = 0.f;
    for (int sp = part; sp < 1024; sp += 8)
        s += base[sp * 64 + d];

    __shared__ float red[512];
    red[tid] = s;
    __syncthreads();
    if (part < 4) red[tid] += red[tid + 256];
    __syncthreads();
    if (part < 2) red[tid] += red[tid + 128];
    __syncthreads();
    if (part == 0) g_u[bn * 64 + d] = red[tid] + red[tid + 64];
}

// ---------------- w[b,:] = LN(u[b,:]) * g1 + beta1 ---------------------------
__global__ __launch_bounds__(256)
void ln_u_kernel(const float* __restrict__ g1, const float* __restrict__ be1)
{
    const int b   = blockIdx.x;
    const int tid = threadIdx.x;
    const float* u = g_u + b * EMBED;

    float x0 = u[tid], x1 = u[tid + 256], x2 = u[tid + 512];
    __shared__ float rs[256], rq[256];
    rs[tid] = x0 + x1 + x2;
    rq[tid] = x0 * x0 + x1 * x1 + x2 * x2;
    __syncthreads();
    for (int off = 128; off > 0; off >>= 1) {
        if (tid < off) { rs[tid] += rs[tid + off]; rq[tid] += rq[tid + off]; }
        __syncthreads();
    }
    __shared__ float s_mu, s_rstd;
    if (tid == 0) {
        float mu = rs[0] * (1.f / EMBED);
        float var = rq[0] * (1.f / EMBED) - mu * mu;
        s_mu = mu; s_rstd = rsqrtf(var + 1e-5f);
    }
    __syncthreads();
    float* w = g_w + b * EMBED;
    w[tid]       = (x0 - s_mu) * s_rstd * g1[tid]       + be1[tid];
    w[tid + 256] = (x1 - s_mu) * s_rstd * g1[tid + 256] + be1[tid + 256];
    w[tid + 512] = (x2 - s_mu) * s_rstd * g1[tid + 512] + be1[tid + 512];
}

// ---------------- wb1[b,n] = b1[n] + sum_k w[b,k] * W1[k,n] ------------------
// 24 blocks (64 cols each), 256 threads = 64 cols x 4 k-chunks; W1 read once.
__global__ __launch_bounds__(256)
void wb1_kernel(const float* __restrict__ W1, const float* __restrict__ b1)
{
    __shared__ float ws[NB * EMBED];           // 24 KB
    __shared__ float part[4 * 64 * NB];        // 8 KB
    const int tid = threadIdx.x;
    for (int i = tid; i < NB * EMBED; i += 256) ws[i] = g_w[i];
    __syncthreads();

    const int colL = tid & 63;
    const int col  = blockIdx.x * 64 + colL;
    const int kc   = tid >> 6;                 // 0..3, 192 k each
    float acc[NB];
    #pragma unroll
    for (int b = 0; b < NB; b++) acc[b] = 0.f;
    const int k0 = kc * 192;
    for (int k = k0; k < k0 + 192; k++) {
        const float wv = W1[(size_t)k * HID + col];
        #pragma unroll
        for (int b = 0; b < NB; b++) acc[b] += ws[b * EMBED + k] * wv;
    }
    #pragma unroll
    for (int b = 0; b < NB; b++) part[(kc * 64 + colL) * NB + b] = acc[b];
    __syncthreads();
    if (kc == 0) {
        const float bb = b1[col];
        #pragma unroll
        for (int b = 0; b < NB; b++) {
            float s = part[(colL) * NB + b] + part[(64 + colL) * NB + b]
                    + part[(128 + colL) * NB + b] + part[(192 + colL) * NB + b];
            g_wb1[b * HID + col] = s + bb;
        }
    }
}

// ---------------- out = x + LN(M)*g2 + beta2 ---------------------------------
__global__ __launch_bounds__(256)
void final_kernel(const float* __restrict__ x, const float* __restrict__ g2,
                  const float* __restrict__ be2, float* __restrict__ out)
{
    const size_t row = blockIdx.x;
    const int tid = threadIdx.x;
    const float* mr = g_M + row * EMBED;
    const float* xr = x   + row * EMBED;

    float a0 = mr[tid], a1 = mr[tid + 256], a2 = mr[tid + 512];
    __shared__ float rs[256], rq[256];
    rs[tid] = a0 + a1 + a2;
    rq[tid] = a0 * a0 + a1 * a1 + a2 * a2;
    __syncthreads();
    for (int off = 128; off > 0; off >>= 1) {
        if (tid < off) { rs[tid] += rs[tid + off]; rq[tid] += rq[tid + off]; }
        __syncthreads();
    }
    __shared__ float s_mu, s_rstd;
    if (tid == 0) {
        float mu = rs[0] * (1.f / EMBED);
        float var = rq[0] * (1.f / EMBED) - mu * mu;
        s_mu = mu; s_rstd = rsqrtf(var + 1e-5f);
    }
    __syncthreads();
    float* o = out + row * EMBED;
    o[tid]       = xr[tid]       + (a0 - s_mu) * s_rstd * g2[tid]       + be2[tid];
    o[tid + 256] = xr[tid + 256] + (a1 - s_mu) * s_rstd * g2[tid + 256] + be2[tid + 256];
    o[tid + 512] = xr[tid + 512] + (a2 - s_mu) * s_rstd * g2[tid + 512] + be2[tid + 512];
}

// ---------------------------------------------------------------------------
extern "C" void kernel_launch(void* const* d_in, const int* in_sizes, int n_in,
                              void* d_out, int out_size)
{
    const float* x   = (const float*)d_in[0];
    // d_in[1]=Wq, d_in[2]=Wk : provably dead (softmax rows sum to 1; the
    // einsum 'bnqk,bnvd->bnqd' factorizes into (sum_k attn)*(sum_v v)).
    const float* Wv  = (const float*)d_in[3];
    const float* W1  = (const float*)d_in[4];
    const float* b1  = (const float*)d_in[5];
    const float* W2  = (const float*)d_in[6];
    const float* b2  = (const float*)d_in[7];
    const float* g1  = (const float*)d_in[8];
    const float* be1 = (const float*)d_in[9];
    const float* g2  = (const float*)d_in[10];
    const float* be2 = (const float*)d_in[11];
    float* out = (float*)d_out;

    float *pV, *pHp, *pM, *pXrp, *pWvP, *pW1P, *pW2P, *pWb1;
    cudaGetSymbolAddress((void**)&pV,   g_V);
    cudaGetSymbolAddress((void**)&pHp,  g_Hp);
    cudaGetSymbolAddress((void**)&pM,   g_M);
    cudaGetSymbolAddress((void**)&pXrp, g_xrp);
    cudaGetSymbolAddress((void**)&pWvP, g_WvP);
    cudaGetSymbolAddress((void**)&pW1P, g_W1P);
    cudaGetSymbolAddress((void**)&pW2P, g_W2P);
    cudaGetSymbolAddress((void**)&pWb1, g_wb1);

    cudaFuncSetAttribute(gemm_p<false,false,false,false,false>,
                         cudaFuncAttributeMaxDynamicSharedMemorySize, GEMM_SMEM);
    cudaFuncSetAttribute(gemm_p<true,true,true,true,true>,
                         cudaFuncAttributeMaxDynamicSharedMemorySize, GEMM_SMEM);
    cudaFuncSetAttribute(gemm_p<false,true,true,false,false>,
                         cudaFuncAttributeMaxDynamicSharedMemorySize, GEMM_SMEM);

    // Launch order arranged so the 4th launch (the one ncu profiles with
    // -s/-c bounds) is GEMM1 — gives mainloop metrics next round.
    // 1) perm Wv
    perm_B<<<(EMBED*EMBED/2)/256, 256>>>(Wv, pWvP, EMBED, EMBED);
    // 2) perm x
    perm_A<<<((size_t)ROWS*EMBED/4)/256, 256>>>(x, pXrp, EMBED);
    // 3) perm W1
    perm_B<<<(EMBED*HID/2)/256,   256>>>(W1, pW1P, EMBED, HID);
    // 4) V = x @ Wv                      (8192 x 768 x 768)   <-- profiled
    gemm_p<false,false,false,false,false><<<dim3(EMBED/128, ROWS/128), 128, GEMM_SMEM>>>(
        pXrp, pWvP, nullptr, pV, ROWS, EMBED, EMBED);
    // 5) perm W2
    perm_B<<<(HID*EMBED/2)/256,   256>>>(W2, pW2P, HID, EMBED);
    // 6) u[b, n*64+d] = strided chunk reduction of V
    vsum_kernel<<<NB * 12, 512>>>();
    // 7) w[b,:] = LN(u[b,:]) * g1 + beta1
    ln_u_kernel<<<NB, 256>>>(g1, be1);
    // 8) wb1[b,:] = b1 + w[b] @ W1   (linearity: (x+w)@W1 = x@W1 + w@W1)
    wb1_kernel<<<HID/64, 256>>>(W1, b1);
    // 9) Hp = perm(tf32(gelu(x@W1 + wb1[b])))   (8192 x 1536 x 768)
    gemm_p<true,true,true,true,true><<<dim3(HID/128, ROWS/128), 128, GEMM_SMEM>>>(
        pXrp, pW1P, pWb1, pHp, ROWS, HID, EMBED);
    // 10) M = gelu(H @ W2 + b2)          (8192 x 768 x 1536)
    gemm_p<false,true,true,false,false><<<dim3(EMBED/128, ROWS/128), 128, GEMM_SMEM>>>(
        pHp, pW2P, b2, pM, ROWS, EMBED, HID);
    // 11) out = x + LN(M) * g2 + beta2
    final_kernel<<<ROWS, 256>>>(x, g2, be2, out);
}

// round 11
// speedup vs baseline: 1.1720x; 1.1720x over previous
#include <cuda_runtime.h>
#include <math.h>
#include <stdint.h>

#define EMBED 768
#define NB    8
#define SEQ   1024
#define ROWS  (NB*SEQ)   // 8192
#define HID   1536

// ---------------- scratch (__device__ globals; no allocs allowed) -----------
__device__ float g_V[(size_t)ROWS*EMBED];
__device__ float g_u[NB*EMBED];
__device__ float g_w[NB*EMBED];
__device__ float g_wb1[NB*HID];               // b1 + w[b] @ W1
__device__ float g_xrp[(size_t)ROWS*EMBED];   // perm(tf32(x))
__device__ float g_Hp[(size_t)ROWS*HID];      // perm(tf32(gelu(..))) from GEMM2
__device__ float g_M[(size_t)ROWS*EMBED];
__device__ float g_WvP[(size_t)EMBED*EMBED];  // perm B frags
__device__ float g_W1P[(size_t)HID*EMBED];
__device__ float g_W2P[(size_t)EMBED*HID];

// ---------------- helpers ----------------------------------------------------
__device__ __forceinline__ float f_tf32(float f) {
    uint32_t r;
    asm("cvt.rna.tf32.f32 %0, %1;" : "=r"(r) : "f"(f));
    return __uint_as_float(r);
}

// exact-GELU via Abramowitz-Stegun erf (abs err 1.5e-7)
__device__ __forceinline__ float gelu_f(float v) {
    float xs = v * 0.70710678118654752f;
    float ax = fabsf(xs);
    float t  = __frcp_rn(1.0f + 0.3275911f * ax);
    float poly = t * (0.254829592f + t * (-0.284496736f +
                 t * (1.421413741f + t * (-1.453152027f + t * 1.061405429f))));
    float erfv = 1.0f - poly * __expf(-ax * ax);
    erfv = copysignf(erfv, xs);
    return 0.5f * v * (1.0f + erfv);
}

__device__ __forceinline__ void mma_tf32(float c[4], const uint32_t a[4], const uint32_t b[2]) {
    asm volatile(
        "mma.sync.aligned.m16n8k8.row.col.f32.tf32.tf32.f32 "
        "{%0,%1,%2,%3}, {%4,%5,%6,%7}, {%8,%9}, {%0,%1,%2,%3};"
        : "+f"(c[0]), "+f"(c[1]), "+f"(c[2]), "+f"(c[3])
        : "r"(a[0]), "r"(a[1]), "r"(a[2]), "r"(a[3]), "r"(b[0]), "r"(b[1]));
}

__device__ __forceinline__ void cp16(uint32_t dst, const void* src) {
    asm volatile("cp.async.cg.shared.global [%0], [%1], 16;" :: "r"(dst), "l"(src));
}
__device__ __forceinline__ void cp_commit() {
    asm volatile("cp.async.commit_group;" ::: "memory");
}
template<int N> __device__ __forceinline__ void cp_wait() {
    asm volatile("cp.async.wait_group %0;" :: "n"(N) : "memory");
}

// ---------------- permuted-layout GEMM --------------------------------------
// A stored as fragment tiles: tile (rt=m/16, kt=k/8): 128 floats [lane][4],
//   slot0=(r,c) slot1=(r+8,c) slot2=(r,c+4) slot3=(r+8,c+4), r=lane>>2, c=lane&3
// B stored as: tile (nt=n/8, kt=k/8): 64 floats [lane][2],
//   slot0=(k=lane&3, n=lane>>2) slot1=(k+4, n)
// CTA 128x128, 256 thr (8 warps 2x4), warp 64x32, BK=32, 3-stage cp.async.
// ONE barrier per k-chunk: stage s=j%3 is only overwritten by the prefetch at
// iter j+1, which follows iter j+1's leading barrier, which follows iter j's
// compute on every thread -> trailing barrier was redundant.
// __launch_bounds__(256, 2): cap regs at 128 so 2 CTAs/SM actually resident.
#define STG 3
#define STAGEF 8192                    // floats/stage: A 4096 + B 4096
#define GEMM_SMEM (STG * STAGEF * 4)   // 98304 B

template<bool BBIAS, bool BIAS, bool GELU, bool CVT, bool PERMOUT>
__global__ __launch_bounds__(256, 2)
void gemm_p(const float* __restrict__ Ap, const float* __restrict__ Bp,
            const float* __restrict__ bias, float* __restrict__ C,
            int M, int N, int K)
{
    extern __shared__ float sm[];
    const int tid  = threadIdx.x;
    const int lane = tid & 31;
    const int warp = tid >> 5;
    const int wm = (warp & 1) * 64;
    const int wn = (warp >> 1) * 32;
    const int rowBase = blockIdx.y * 128;
    const int colBase = blockIdx.x * 128;
    const int KT8 = K >> 3;
    const int rowTile0 = blockIdx.y * 8;
    const int colTile0 = blockIdx.x * 16;
    const uint32_t smBase = (uint32_t)__cvta_generic_to_shared(sm);

    float acc[4][4][4];
    #pragma unroll
    for (int i = 0; i < 4; i++)
        #pragma unroll
        for (int j = 0; j < 4; j++)
            #pragma unroll
            for (int c = 0; c < 4; c++) acc[i][j][c] = 0.f;

    const int NC = K >> 5;

    // stage copy: 1024 A cp16 + 1024 B cp16 by 256 threads
    auto stage_copy = [&](int s, int ktBase) {
        const uint32_t aB = smBase + (uint32_t)(s * STAGEF * 4);
        const uint32_t bB = aB + 16384;
        #pragma unroll
        for (int u = 0; u < 4; u++) {
            const int i  = tid + 256 * u;
            const int rt = i >> 7, kt = (i >> 5) & 3, l = i & 31;
            cp16(aB + (uint32_t)i * 16,
                 Ap + ((size_t)(rowTile0 + rt) * KT8 + ktBase + kt) * 128 + l * 4);
        }
        #pragma unroll
        for (int u = 0; u < 4; u++) {
            const int j  = tid + 256 * u;
            const int nt = j >> 6, kt = (j >> 4) & 3, p = j & 15;
            cp16(bB + (uint32_t)j * 16,
                 Bp + ((size_t)(colTile0 + nt) * KT8 + ktBase + kt) * 64 + p * 4);
        }
        cp_commit();
    };

    stage_copy(0, 0);
    stage_copy(1, 4);

    for (int j = 0; j < NC; j++) {
        if (j + 1 < NC) cp_wait<1>(); else cp_wait<0>();
        __syncthreads();

        if (j + 2 < NC) stage_copy((j + 2) % STG, (j + 2) * 4);

        const float* As_ = sm + (j % STG) * STAGEF;
        const float* Bs_ = As_ + 4096;
        #pragma unroll
        for (int kt = 0; kt < 4; kt++) {
            uint32_t afr[4][4];
            #pragma unroll
            for (int mt = 0; mt < 4; mt++) {
                const float4 v = *(const float4*)(
                    As_ + (((warp & 1) * 4 + mt) * 4 + kt) * 128 + lane * 4);
                afr[mt][0] = __float_as_uint(v.x);
                afr[mt][1] = __float_as_uint(v.y);
                afr[mt][2] = __float_as_uint(v.z);
                afr[mt][3] = __float_as_uint(v.w);
            }
            uint32_t bfr[4][2];
            #pragma unroll
            for (int nt = 0; nt < 4; nt++) {
                const float2 v = *(const float2*)(
                    Bs_ + (((warp >> 1) * 4 + nt) * 4 + kt) * 64 + lane * 2);
                bfr[nt][0] = __float_as_uint(v.x);
                bfr[nt][1] = __float_as_uint(v.y);
            }
            #pragma unroll
            for (int mt = 0; mt < 4; mt++)
                #pragma unroll
                for (int nt = 0; nt < 4; nt++)
                    mma_tf32(acc[mt][nt], afr[mt], bfr[nt]);
        }
        // no trailing barrier: next iteration's leading barrier protects the
        // stage from being overwritten (see header comment).
    }
    __syncthreads();   // protect smem reuse by the PERMOUT epilogue

    // epilogue
    const float* bp = BBIAS ? (bias + (size_t)(rowBase >> 10) * N) : bias;

    if (PERMOUT) {
        // stage permuted tile in smem (pipeline stages are dead now), then
        // copy out with fully coalesced float4 stores.
        #pragma unroll
        for (int mt = 0; mt < 4; mt++) {
            const int rt_l = (warp & 1) * 4 + mt;   // local m-tile 0..7
            #pragma unroll
            for (int nt = 0; nt < 4; nt++) {
                const int kt_l = (warp >> 1) * 4 + nt;  // local k-tile 0..15
                const int col = colBase + wn + nt * 8 + 2 * (lane & 3);
                float v0 = acc[mt][nt][0], v1 = acc[mt][nt][1];
                float v2 = acc[mt][nt][2], v3 = acc[mt][nt][3];
                if (BIAS) {
                    float b0 = bp[col], b1v = bp[col + 1];
                    v0 += b0; v1 += b1v; v2 += b0; v3 += b1v;
                }
                if (GELU) {
                    v0 = gelu_f(v0); v1 = gelu_f(v1);
                    v2 = gelu_f(v2); v3 = gelu_f(v3);
                }
                if (CVT) {
                    v0 = f_tf32(v0); v1 = f_tf32(v1);
                    v2 = f_tf32(v2); v3 = f_tf32(v3);
                }
                float* base = sm + (rt_l * 16 + kt_l) * 128;
                const int r    = lane >> 2;
                const int cc   = 2 * (lane & 3);
                const int cp_  = cc & 3;
                const int slot = (cc < 4) ? 0 : 2;
                base[(4*r + cp_    ) * 4 + slot    ] = v0;
                base[(4*r + cp_ + 1) * 4 + slot    ] = v1;
                base[(4*r + cp_    ) * 4 + slot + 1] = v2;
                base[(4*r + cp_ + 1) * 4 + slot + 1] = v3;
            }
        }
        __syncthreads();
        // 8 rt-rows, each 16 tiles * 128 floats = 2048 floats contiguous in
        // both smem and global. 4096 float4 total / 256 threads = 16 each.
        #pragma unroll
        for (int u = 0; u < 16; u++) {
            const int i   = u * 256 + tid;
            const int rt  = i >> 9;          // 0..7
            const int idx = i & 511;         // float4 index within row
            const float4 v = ((const float4*)(sm + rt * 2048))[idx];
            ((float4*)(C + ((size_t)(rowTile0 + rt) * (N >> 3) + colTile0) * 128))[idx] = v;
        }
    } else {
        #pragma unroll
        for (int mt = 0; mt < 4; mt++) {
            const int r0 = rowBase + wm + mt * 16 + (lane >> 2);
            #pragma unroll
            for (int nt = 0; nt < 4; nt++) {
                const int col = colBase + wn + nt * 8 + 2 * (lane & 3);
                float v0 = acc[mt][nt][0], v1 = acc[mt][nt][1];
                float v2 = acc[mt][nt][2], v3 = acc[mt][nt][3];
                if (BIAS) {
                    float b0 = bp[col], b1v = bp[col + 1];
                    v0 += b0; v1 += b1v; v2 += b0; v3 += b1v;
                }
                if (GELU) {
                    v0 = gelu_f(v0); v1 = gelu_f(v1);
                    v2 = gelu_f(v2); v3 = gelu_f(v3);
                }
                if (CVT) {
                    v0 = f_tf32(v0); v1 = f_tf32(v1);
                    v2 = f_tf32(v2); v3 = f_tf32(v3);
                }
                *(float2*)(C + (size_t)r0 * N + col)       = make_float2(v0, v1);
                *(float2*)(C + (size_t)(r0 + 8) * N + col) = make_float2(v2, v3);
            }
        }
    }
}

// ---------------- perm A: [M,K] normal -> fragment tiles (+tf32) -------------
__global__ __launch_bounds__(256)
void perm_A(const float* __restrict__ in, float* __restrict__ out, int K)
{
    const size_t p4 = (size_t)blockIdx.x * 256 + threadIdx.x;  // one lane-quad
    const int KT8 = K >> 3;
    const size_t tile = p4 >> 5;
    const int l  = (int)(p4 & 31);
    const int rt = (int)(tile / KT8), kt = (int)(tile % KT8);
    const int r = rt * 16 + (l >> 2);
    const int c = kt * 8 + (l & 3);
    const float* row0 = in + (size_t)r * K;
    const float* row8 = row0 + (size_t)8 * K;
    float4 o;
    o.x = f_tf32(row0[c]);
    o.y = f_tf32(row8[c]);
    o.z = f_tf32(row0[c + 4]);
    o.w = f_tf32(row8[c + 4]);
    *(float4*)(out + p4 * 4) = o;
}

// ---------------- perm B: W[K,N] normal -> fragment tiles (+tf32) ------------
__global__ __launch_bounds__(256)
void perm_B(const float* __restrict__ W, float* __restrict__ out, int K, int N)
{
    const size_t p2 = (size_t)blockIdx.x * 256 + threadIdx.x;  // one lane-pair
    const int KT8 = K >> 3;
    const size_t tile = p2 >> 5;
    const int l  = (int)(p2 & 31);
    const int nt = (int)(tile / KT8), kt = (int)(tile % KT8);
    const int n = nt * 8 + (l >> 2);
    const int k = kt * 8 + (l & 3);
    float2 o;
    o.x = f_tf32(W[(size_t)k * N + n]);
    o.y = f_tf32(W[(size_t)(k + 4) * N + n]);
    *(float2*)(out + p2 * 2) = o;
}

// ---------------- vsum: u[b,n*64+d] = sum_s V_chunk[b,n][64*s+d] -------------
__global__ __launch_bounds__(512)
void vsum_kernel()
{
    const int bn  = blockIdx.x;
    const int tid = threadIdx.x;
    const int d    = tid & 63;
    const int part = tid >> 6;
    const float* base = g_V + (size_t)bn * 65536;

    float s = 0.f;
    for (int sp = part; sp < 1024; sp += 8)
        s += base[sp * 64 + d];

    __shared__ float red[512];
    red[tid] = s;
    __syncthreads();
    if (part < 4) red[tid] += red[tid + 256];
    __syncthreads();
    if (part < 2) red[tid] += red[tid + 128];
    __syncthreads();
    if (part == 0) g_u[bn * 64 + d] = red[tid] + red[tid + 64];
}

// ---------------- w[b,:] = LN(u[b,:]) * g1 + beta1 ---------------------------
__global__ __launch_bounds__(256)
void ln_u_kernel(const float* __restrict__ g1, const float* __restrict__ be1)
{
    const int b   = blockIdx.x;
    const int tid = threadIdx.x;
    const float* u = g_u + b * EMBED;

    float x0 = u[tid], x1 = u[tid + 256], x2 = u[tid + 512];
    __shared__ float rs[256], rq[256];
    rs[tid] = x0 + x1 + x2;
    rq[tid] = x0 * x0 + x1 * x1 + x2 * x2;
    __syncthreads();
    for (int off = 128; off > 0; off >>= 1) {
        if (tid < off) { rs[tid] += rs[tid + off]; rq[tid] += rq[tid + off]; }
        __syncthreads();
    }
    __shared__ float s_mu, s_rstd;
    if (tid == 0) {
        float mu = rs[0] * (1.f / EMBED);
        float var = rq[0] * (1.f / EMBED) - mu * mu;
        s_mu = mu; s_rstd = rsqrtf(var + 1e-5f);
    }
    __syncthreads();
    float* w = g_w + b * EMBED;
    w[tid]       = (x0 - s_mu) * s_rstd * g1[tid]       + be1[tid];
    w[tid + 256] = (x1 - s_mu) * s_rstd * g1[tid + 256] + be1[tid + 256];
    w[tid + 512] = (x2 - s_mu) * s_rstd * g1[tid + 512] + be1[tid + 512];
}

// ---------------- wb1[b,n] = b1[n] + sum_k w[b,k] * W1[k,n] ------------------
// 24 blocks (64 cols each), 256 threads = 64 cols x 4 k-chunks; W1 read once.
__global__ __launch_bounds__(256)
void wb1_kernel(const float* __restrict__ W1, const float* __restrict__ b1)
{
    __shared__ float ws[NB * EMBED];           // 24 KB
    __shared__ float part[4 * 64 * NB];        // 8 KB
    const int tid = threadIdx.x;
    for (int i = tid; i < NB * EMBED; i += 256) ws[i] = g_w[i];
    __syncthreads();

    const int colL = tid & 63;
    const int col  = blockIdx.x * 64 + colL;
    const int kc   = tid >> 6;                 // 0..3, 192 k each
    float acc[NB];
    #pragma unroll
    for (int b = 0; b < NB; b++) acc[b] = 0.f;
    const int k0 = kc * 192;
    for (int k = k0; k < k0 + 192; k++) {
        const float wv = W1[(size_t)k * HID + col];
        #pragma unroll
        for (int b = 0; b < NB; b++) acc[b] += ws[b * EMBED + k] * wv;
    }
    #pragma unroll
    for (int b = 0; b < NB; b++) part[(kc * 64 + colL) * NB + b] = acc[b];
    __syncthreads();
    if (kc == 0) {
        const float bb = b1[col];
        #pragma unroll
        for (int b = 0; b < NB; b++) {
            float s = part[(colL) * NB + b] + part[(64 + colL) * NB + b]
                    + part[(128 + colL) * NB + b] + part[(192 + colL) * NB + b];
            g_wb1[b * HID + col] = s + bb;
        }
    }
}

// ---------------- out = x + LN(M)*g2 + beta2 ---------------------------------
__global__ __launch_bounds__(256)
void final_kernel(const float* __restrict__ x, const float* __restrict__ g2,
                  const float* __restrict__ be2, float* __restrict__ out)
{
    const size_t row = blockIdx.x;
    const int tid = threadIdx.x;
    const float* mr = g_M + row * EMBED;
    const float* xr = x   + row * EMBED;

    float a0 = mr[tid], a1 = mr[tid + 256], a2 = mr[tid + 512];
    __shared__ float rs[256], rq[256];
    rs[tid] = a0 + a1 + a2;
    rq[tid] = a0 * a0 + a1 * a1 + a2 * a2;
    __syncthreads();
    for (int off = 128; off > 0; off >>= 1) {
        if (tid < off) { rs[tid] += rs[tid + off]; rq[tid] += rq[tid + off]; }
        __syncthreads();
    }
    __shared__ float s_mu, s_rstd;
    if (tid == 0) {
        float mu = rs[0] * (1.f / EMBED);
        float var = rq[0] * (1.f / EMBED) - mu * mu;
        s_mu = mu; s_rstd = rsqrtf(var + 1e-5f);
    }
    __syncthreads();
    float* o = out + row * EMBED;
    o[tid]       = xr[tid]       + (a0 - s_mu) * s_rstd * g2[tid]       + be2[tid];
    o[tid + 256] = xr[tid + 256] + (a1 - s_mu) * s_rstd * g2[tid + 256] + be2[tid + 256];
    o[tid + 512] = xr[tid + 512] + (a2 - s_mu) * s_rstd * g2[tid + 512] + be2[tid + 512];
}

// ---------------------------------------------------------------------------
extern "C" void kernel_launch(void* const* d_in, const int* in_sizes, int n_in,
                              void* d_out, int out_size)
{
    const float* x   = (const float*)d_in[0];
    // d_in[1]=Wq, d_in[2]=Wk : provably dead (softmax rows sum to 1; the
    // einsum 'bnqk,bnvd->bnqd' factorizes into (sum_k attn)*(sum_v v)).
    const float* Wv  = (const float*)d_in[3];
    const float* W1  = (const float*)d_in[4];
    const float* b1  = (const float*)d_in[5];
    const float* W2  = (const float*)d_in[6];
    const float* b2  = (const float*)d_in[7];
    const float* g1  = (const float*)d_in[8];
    const float* be1 = (const float*)d_in[9];
    const float* g2  = (const float*)d_in[10];
    const float* be2 = (const float*)d_in[11];
    float* out = (float*)d_out;

    float *pV, *pHp, *pM, *pXrp, *pWvP, *pW1P, *pW2P, *pWb1;
    cudaGetSymbolAddress((void**)&pV,   g_V);
    cudaGetSymbolAddress((void**)&pHp,  g_Hp);
    cudaGetSymbolAddress((void**)&pM,   g_M);
    cudaGetSymbolAddress((void**)&pXrp, g_xrp);
    cudaGetSymbolAddress((void**)&pWvP, g_WvP);
    cudaGetSymbolAddress((void**)&pW1P, g_W1P);
    cudaGetSymbolAddress((void**)&pW2P, g_W2P);
    cudaGetSymbolAddress((void**)&pWb1, g_wb1);

    cudaFuncSetAttribute(gemm_p<false,false,false,false,false>,
                         cudaFuncAttributeMaxDynamicSharedMemorySize, GEMM_SMEM);
    cudaFuncSetAttribute(gemm_p<true,true,true,true,true>,
                         cudaFuncAttributeMaxDynamicSharedMemorySize, GEMM_SMEM);
    cudaFuncSetAttribute(gemm_p<false,true,true,false,false>,
                         cudaFuncAttributeMaxDynamicSharedMemorySize, GEMM_SMEM);

    // Launch order keeps GEMM1 as the 4th launch (the one ncu profiles).
    // 1) perm Wv
    perm_B<<<(EMBED*EMBED/2)/256, 256>>>(Wv, pWvP, EMBED, EMBED);
    // 2) perm x
    perm_A<<<((size_t)ROWS*EMBED/4)/256, 256>>>(x, pXrp, EMBED);
    // 3) perm W1
    perm_B<<<(EMBED*HID/2)/256,   256>>>(W1, pW1P, EMBED, HID);
    // 4) V = x @ Wv                      (8192 x 768 x 768)   <-- profiled
    gemm_p<false,false,false,false,false><<<dim3(EMBED/128, ROWS/128), 256, GEMM_SMEM>>>(
        pXrp, pWvP, nullptr, pV, ROWS, EMBED, EMBED);
    // 5) perm W2
    perm_B<<<(HID*EMBED/2)/256,   256>>>(W2, pW2P, HID, EMBED);
    // 6) u[b, n*64+d] = strided chunk reduction of V
    vsum_kernel<<<NB * 12, 512>>>();
    // 7) w[b,:] = LN(u[b,:]) * g1 + beta1
    ln_u_kernel<<<NB, 256>>>(g1, be1);
    // 8) wb1[b,:] = b1 + w[b] @ W1   (linearity: (x+w)@W1 = x@W1 + w@W1)
    wb1_kernel<<<HID/64, 256>>>(W1, b1);
    // 9) Hp = perm(tf32(gelu(x@W1 + wb1[b])))   (8192 x 1536 x 768)
    gemm_p<true,true,true,true,true><<<dim3(HID/128, ROWS/128), 256, GEMM_SMEM>>>(
        pXrp, pW1P, pWb1, pHp, ROWS, HID, EMBED);
    // 10) M = gelu(H @ W2 + b2)          (8192 x 768 x 1536)
    gemm_p<false,true,true,false,false><<<dim3(EMBED/128, ROWS/128), 256, GEMM_SMEM>>>(
        pHp, pW2P, b2, pM, ROWS, EMBED, HID);
    // 11) out = x + LN(M) * g2 + beta2
    final_kernel<<<ROWS, 256>>>(x, g2, be2, out);
}